// round 13
// baseline (speedup 1.0000x reference)
#include <cuda_runtime.h>
#include <cuda_bf16.h>
#include <cstdint>

// ChempropBlock: V=10000 nodes, E=160000 edges, D=512, DEPTH=3
// out = [node_hiddens (V*D) | eh (E*D)] fp32
//
// Per layer l:
//   k_edge_split: em_frag = split_bf16(nm[src] - relu(eh[rev])) in the GEMM's
//                 fragment tile layout (gather+convert off the GEMM path)
//   k_gemm_mma:   streaming 3-stage cp.async pipeline; eh += em @ W^T + b
//                 (in place); epilogue scatters relu(eh) into nm_next
//                 (plain into out_nodes on the last layer).
// GEMM math: mma.sync m16n8k16 bf16, 3-term split (D += A0B0 + A1B0 + A0B1).
// R13: MMA loop restructured into 3 passes of 16 independent MMAs (acc RAW
// distance 4 -> 16); wfrag+zero fused into k_setup so ncu captures gemm0.

#define V_N 10000
#define E_N 160000
#define D_N 512
#define DEPTH_N 3

#define TM 128
#define TN 128
#define KC 32
#define NCHUNK (D_N / KC)     // 16
#define NMB (E_N / TM)        // 1250 m-blocks
#define CH_U32 4096           // u32 per (mblock, chunk) fragment block
#define MB_U32 (NCHUNK * CH_U32)   // 65536 u32 per mblock

__device__ float g_nm0[(size_t)V_N * D_N];
__device__ float g_nm1[(size_t)V_N * D_N];
__device__ float g_nm2[(size_t)V_N * D_N];
// em fragment buffer: [mb(1250)][chunk(16)][sp(2)][row(128)][16 u32] = 327 MB
__device__ uint32_t g_em[(size_t)NMB * MB_U32];
// W fragments: [layer(3)][nblock(4)][chunk(16)][k16(2)][nb(16)][lane(32)] uint4
__device__ uint4 g_wfrag[3 * 4 * 16 * 2 * 16 * 32];

__device__ __forceinline__ uint32_t smem_u32(const void* p) {
    uint32_t a;
    asm("{ .reg .u64 t; cvta.to.shared.u64 t, %1; cvt.u32.u64 %0, t; }"
        : "=r"(a) : "l"(p));
    return a;
}
__device__ __forceinline__ uint32_t pack_bf2(float x, float y, float2& back) {
    __nv_bfloat162 h = __float22bfloat162_rn(make_float2(x, y));
    back = __bfloat1622float2(h);
    return *(uint32_t*)&h;
}
__device__ __forceinline__ uint32_t pack_bf2n(float x, float y) {
    __nv_bfloat162 h = __float22bfloat162_rn(make_float2(x, y));
    return *(uint32_t*)&h;
}
__device__ __forceinline__ void red_add_v4(float* addr, float4 v) {
    asm volatile("red.global.add.v4.f32 [%0], {%1, %2, %3, %4};"
                 :: "l"(addr), "f"(v.x), "f"(v.y), "f"(v.z), "f"(v.w)
                 : "memory");
}
__device__ __forceinline__ void red_add_v2(float* addr, float x, float y) {
    asm volatile("red.global.add.v2.f32 [%0], {%1, %2};"
                 :: "l"(addr), "f"(x), "f"(y)
                 : "memory");
}
__device__ __forceinline__ void ldmatrix_x4(uint32_t* r, uint32_t addr) {
    asm volatile("ldmatrix.sync.aligned.m8n8.x4.shared.b16 {%0,%1,%2,%3}, [%4];"
                 : "=r"(r[0]), "=r"(r[1]), "=r"(r[2]), "=r"(r[3])
                 : "r"(addr));
}
__device__ __forceinline__ void mma_bf16(float* d, const uint32_t* a,
                                         uint32_t b0, uint32_t b1) {
    asm volatile(
        "mma.sync.aligned.m16n8k16.row.col.f32.bf16.bf16.f32 "
        "{%0,%1,%2,%3}, {%4,%5,%6,%7}, {%8,%9}, {%0,%1,%2,%3};"
        : "+f"(d[0]), "+f"(d[1]), "+f"(d[2]), "+f"(d[3])
        : "r"(a[0]), "r"(a[1]), "r"(a[2]), "r"(a[3]), "r"(b0), "r"(b1));
}

#define CP_ASYNC_16(dst_u32, src_ptr) \
    asm volatile("cp.async.cg.shared.global [%0], [%1], 16;" \
                 :: "r"(dst_u32), "l"(src_ptr) : "memory")
#define CP_ASYNC_COMMIT() asm volatile("cp.async.commit_group;" ::: "memory")
#define CP_ASYNC_WAIT0()  asm volatile("cp.async.wait_group 0;" ::: "memory")
#define CP_ASYNC_WAIT1()  asm volatile("cp.async.wait_group 1;" ::: "memory")

// ---------------------------------------------------------------------------
// setup: zero nm0/nm1/nm2/out_nodes AND precompute W fragments, one launch.
// blocks [0, 20000): zeroing (4 x 1.28M float4); blocks [20000, 20768): wfrag.
// ---------------------------------------------------------------------------
#define ZERO_BLKS 20000
__global__ void k_setup(const float* __restrict__ Ws,
                        float4* __restrict__ z0, float4* __restrict__ z1,
                        float4* __restrict__ z2, float4* __restrict__ z3) {
    const int bid = blockIdx.x;
    if (bid < ZERO_BLKS) {
        const int n4 = V_N * D_N / 4;          // 1,280,000
        int i = bid * 256 + threadIdx.x;       // < 5,120,000
        int which = i / n4;
        int off = i - which * n4;
        float4* p = (which == 0) ? z0 : (which == 1) ? z1
                  : (which == 2) ? z2 : z3;
        p[off] = make_float4(0.f, 0.f, 0.f, 0.f);
        return;
    }
    int t = (bid - ZERO_BLKS) * 256 + threadIdx.x;   // < 196608
    int lane  = t & 31;
    int nb    = (t >> 5) & 15;
    int k16   = (t >> 9) & 1;
    int chunk = (t >> 10) & 15;
    int nblk  = (t >> 14) & 3;
    int layer = t >> 16;
    int n = nblk * 128 + nb * 8 + (lane >> 2);
    int k = chunk * 32 + k16 * 16 + (lane & 3) * 2;
    const float* w = Ws + ((size_t)layer * D_N + n) * D_N + k;
    float w00 = w[0], w01 = w[1], w10 = w[8], w11 = w[9];
    float2 bk;
    uint4 o;
    o.x = pack_bf2(w00, w01, bk);
    o.z = pack_bf2n(w00 - bk.x, w01 - bk.y);
    o.y = pack_bf2(w10, w11, bk);
    o.w = pack_bf2n(w10 - bk.x, w11 - bk.y);
    g_wfrag[t] = o;
}

// eh0 = nf[src] + ef (written to d_out eh region); relu-scatter eh0 into nm
__global__ void k_init_eh_scatter(const float* __restrict__ nf,
                                  const float* __restrict__ ef,
                                  const int* __restrict__ src,
                                  const int* __restrict__ dst,
                                  float* __restrict__ eh,
                                  float* __restrict__ nm) {
    int idx = blockIdx.x * blockDim.x + threadIdx.x;   // < E*D/4
    int e = idx >> 7;
    int c = (idx & 127) << 2;
    int s = __ldg(&src[e]);
    const float4 a = *(const float4*)(nf + (size_t)s * D_N + c);
    const float4 b = *(const float4*)(ef + (size_t)e * D_N + c);
    float4 r; r.x = a.x + b.x; r.y = a.y + b.y; r.z = a.z + b.z; r.w = a.w + b.w;
    *(float4*)(eh + (size_t)e * D_N + c) = r;
    int d = __ldg(&dst[e]);
    float4 rr;
    rr.x = fmaxf(r.x, 0.f); rr.y = fmaxf(r.y, 0.f);
    rr.z = fmaxf(r.z, 0.f); rr.w = fmaxf(r.w, 0.f);
    red_add_v4(nm + (size_t)d * D_N + c, rr);
}

// ---------------------------------------------------------------------------
// em_frag writer (identical layout + math to R12)
// ---------------------------------------------------------------------------
__global__ void k_edge_split(const float* __restrict__ nm,
                             const float* __restrict__ eh,
                             const int* __restrict__ src,
                             const int* __restrict__ rev) {
    int g = blockIdx.x * blockDim.x + threadIdx.x;   // < E*8
    int row = g >> 3;
    int kp  = g & 7;
    int s = __ldg(&src[row]);
    int r = __ldg(&rev[row]);
    const float* nrow = nm + (size_t)s * D_N + kp * 4;
    const float* erow = eh + (size_t)r * D_N + kp * 4;
    const int mb = row >> 7;
    const int ri = row & 127;
    const int sw = ((ri >> 1) & 3) << 2;
    uint32_t* base = g_em + (size_t)mb * MB_U32 + ri * 16 + ((2 * kp) ^ sw);
#pragma unroll 4
    for (int c = 0; c < NCHUNK; ++c) {
        const float4 n4 = *(const float4*)(nrow + c * KC);
        const float4 e4 = *(const float4*)(erow + c * KC);
        float em0 = n4.x - fmaxf(e4.x, 0.f);
        float em1 = n4.y - fmaxf(e4.y, 0.f);
        float em2 = n4.z - fmaxf(e4.z, 0.f);
        float em3 = n4.w - fmaxf(e4.w, 0.f);
        float2 bk;
        uint2 s0, s1;
        s0.x = pack_bf2(em0, em1, bk);
        s1.x = pack_bf2n(em0 - bk.x, em1 - bk.y);
        s0.y = pack_bf2(em2, em3, bk);
        s1.y = pack_bf2n(em2 - bk.x, em3 - bk.y);
        *(uint2*)(base + c * CH_U32)        = s0;   // split-hi (sp=0)
        *(uint2*)(base + c * CH_U32 + 2048) = s1;   // split-lo (sp=1)
    }
}

// ---------------------------------------------------------------------------
// Streaming GEMM. smem (b32): [0..511] s_dst + pad; 3 stages of 8192:
//   stage: SA = [sp(2)][row(128)][16 u32] (4096), SB = [k16][nb][lane] uint4
// total 25088 u32 = 100352 B -> 2 CTA/SM.
// ---------------------------------------------------------------------------
#define STG_U32 8192
#define SMEM_U32 (512 + 3 * STG_U32)   // 25088

__global__ void __launch_bounds__(256, 2)
k_gemm_mma(const uint4* __restrict__ wf,
           const float* __restrict__ bias,
           const uint32_t* __restrict__ em,
           float* __restrict__ eh,             // in-place update
           const int* __restrict__ dst,
           float* __restrict__ scat,
           int do_relu) {
    extern __shared__ float smemf[];
    uint32_t* smemu = (uint32_t*)smemf;
    int* s_dst = (int*)smemf;

    const int tid = threadIdx.x;
    const int wid = tid >> 5;
    const int lid = tid & 31;
    const int mBase = blockIdx.y * TM;
    const int nBase = blockIdx.x * TN;
    const uint32_t* emb = em + (size_t)blockIdx.y * MB_U32;
    const uint4* wfn = wf + (size_t)blockIdx.x * (NCHUNK * 1024);

    if (tid < TM) s_dst[tid] = __ldg(&dst[mBase + tid]);
    // s_dst read only in the epilogue, long after the pipeline's barriers.

    const uint32_t sb = smem_u32(smemf);

    auto issue = [&](int c, int stg) {
        const uint32_t ab = sb + (512 + stg * STG_U32) * 4;
        const uint32_t* gA = emb + c * CH_U32;
#pragma unroll
        for (int q = 0; q < 4; ++q) {
            const int i = tid + q * 256;
            CP_ASYNC_16(ab + i * 16, gA + i * 4);
        }
        const uint32_t bb = ab + 4096 * 4;
        const uint4* gB = wfn + c * 1024;
#pragma unroll
        for (int q = 0; q < 4; ++q) {
            const int i = tid + q * 256;
            CP_ASYNC_16(bb + i * 16, gB + i);
        }
    };

    // ---- warp tiles: 2 (M) x 4 (N) of 64x32 ----
    const int wm  = (wid >> 2) * 64;
    const int wnb = (wid & 3) * 4;
    const int wn  = wnb * 8;

    const int lmrow = lid & 15;
    const int lmkh  = (lid >> 4) << 2;
    uint32_t lmOff[4], lmSw[4];
#pragma unroll
    for (int rbi = 0; rbi < 4; ++rbi) {
        const int row = wm + rbi * 16 + lmrow;
        lmOff[rbi] = row * 16;
        lmSw[rbi]  = ((row >> 1) & 3) << 2;
    }

    float acc[4][4][4];
#pragma unroll
    for (int i = 0; i < 4; ++i)
#pragma unroll
        for (int j = 0; j < 4; ++j)
#pragma unroll
            for (int k = 0; k < 4; ++k) acc[i][j][k] = 0.f;

    // 3-stage pipeline: issue(0),(1) up front; per chunk:
    //   wait (<=1, last chunk 0) -> barrier -> issue(c+2) -> MMA(c)
    issue(0, 0); CP_ASYNC_COMMIT();
    issue(1, 1); CP_ASYNC_COMMIT();

    for (int c = 0; c < NCHUNK; ++c) {
        const int stg = c % 3;
        if (c == NCHUNK - 1) { CP_ASYNC_WAIT0(); } else { CP_ASYNC_WAIT1(); }
        __syncthreads();
        if (c + 2 < NCHUNK) {
            issue(c + 2, (c + 2) % 3);
            CP_ASYNC_COMMIT();
        }

        const uint32_t sa_base = 512 + stg * STG_U32;
        const uint32_t sb_base = sa_base + 4096;
#pragma unroll
        for (int k16 = 0; k16 < 2; ++k16) {
            // load all operands first (8 LDSM + 4 LDS.128), then 3 passes of
            // 16 independent MMAs: same-acc RAW distance = 16 instructions.
            uint4 b[4];
#pragma unroll
            for (int nb = 0; nb < 4; ++nb)
                b[nb] = *(const uint4*)(smemu + sb_base +
                         ((k16 * 16 + wnb + nb) * 32 + lid) * 4);
            uint32_t as0[4][4], as1[4][4];
#pragma unroll
            for (int rbi = 0; rbi < 4; ++rbi) {
                const uint32_t idx = (uint32_t)((k16 * 8) | lmkh) ^ lmSw[rbi];
                const uint32_t a0addr = sb + (sa_base + lmOff[rbi] + idx) * 4;
                ldmatrix_x4(as0[rbi], a0addr);
                ldmatrix_x4(as1[rbi], a0addr + 2048 * 4);   // split-lo
            }
#pragma unroll
            for (int rbi = 0; rbi < 4; ++rbi)
#pragma unroll
                for (int nb = 0; nb < 4; ++nb)
                    mma_bf16(acc[rbi][nb], as0[rbi], b[nb].x, b[nb].y);
#pragma unroll
            for (int rbi = 0; rbi < 4; ++rbi)
#pragma unroll
                for (int nb = 0; nb < 4; ++nb)
                    mma_bf16(acc[rbi][nb], as1[rbi], b[nb].x, b[nb].y);
#pragma unroll
            for (int rbi = 0; rbi < 4; ++rbi)
#pragma unroll
                for (int nb = 0; nb < 4; ++nb)
                    mma_bf16(acc[rbi][nb], as0[rbi], b[nb].z, b[nb].w);
        }
    }

    // ---- epilogue: eh += acc + bias (in place); fused scatter ----
    const int lr4 = lid >> 2;
    const int lm4 = lid & 3;
#pragma unroll
    for (int rbi = 0; rbi < 4; ++rbi) {
#pragma unroll
        for (int half = 0; half < 2; ++half) {
            const int mi = wm + rbi * 16 + half * 8 + lr4;
            const int m = mBase + mi;
            const int d = s_dst[mi];
            float* erow = eh + (size_t)m * D_N + nBase;
            float* srow = scat + (size_t)d * D_N + nBase;
#pragma unroll
            for (int nb = 0; nb < 4; ++nb) {
                const int cc = wn + nb * 8 + 2 * lm4;
                float2 e = *(const float2*)(erow + cc);
                e.x += acc[rbi][nb][half * 2 + 0] + __ldg(&bias[nBase + cc]);
                e.y += acc[rbi][nb][half * 2 + 1] + __ldg(&bias[nBase + cc + 1]);
                *(float2*)(erow + cc) = e;
                if (do_relu) {
                    red_add_v2(srow + cc, fmaxf(e.x, 0.f), fmaxf(e.y, 0.f));
                } else {
                    red_add_v2(srow + cc, e.x, e.y);
                }
            }
        }
    }
}

// ---------------------------------------------------------------------------
extern "C" void kernel_launch(void* const* d_in, const int* in_sizes, int n_in,
                              void* d_out, int out_size) {
    const float* node_feats = (const float*)d_in[0];
    const float* edge_feats = (const float*)d_in[1];
    const float* Ws         = (const float*)d_in[2];
    const float* bs         = (const float*)d_in[3];
    const int*   edge_index = (const int*)  d_in[4];
    const int*   rev_index  = (const int*)  d_in[5];

    const int* src = edge_index;
    const int* dst = edge_index + E_N;

    float* out_nodes = (float*)d_out;
    float* eh        = (float*)d_out + (size_t)V_N * D_N;   // in-place

    float *nm0 = nullptr, *nm1 = nullptr, *nm2 = nullptr;
    uint32_t* em = nullptr;
    cudaGetSymbolAddress((void**)&nm0, g_nm0);
    cudaGetSymbolAddress((void**)&nm1, g_nm1);
    cudaGetSymbolAddress((void**)&nm2, g_nm2);
    cudaGetSymbolAddress((void**)&em, g_em);
    uint4* wfrag = nullptr;
    cudaGetSymbolAddress((void**)&wfrag, g_wfrag);

    const int smem_bytes = SMEM_U32 * 4;    // 100352
    cudaFuncSetAttribute(k_gemm_mma,
                         cudaFuncAttributeMaxDynamicSharedMemorySize, smem_bytes);

    const int TPB = 256;
    const int edgeGrid  = (E_N * (D_N / 4)) / TPB;      // 80000
    const int splitGrid = (E_N * 8) / TPB;              // 5000
    dim3 gemmGrid(D_N / TN, E_N / TM);                  // (4, 1250)

    // launches: 0 setup(zero+wfrag), 1 init, 2 split0, 3 gemm0 <- ncu capture
    k_setup<<<ZERO_BLKS + 768, TPB>>>(Ws, (float4*)nm0, (float4*)nm1,
                                      (float4*)nm2, (float4*)out_nodes);
    k_init_eh_scatter<<<edgeGrid, TPB>>>(node_feats, edge_feats, src, dst,
                                         eh, nm0);

    float* nmchain[4] = { nm0, nm1, nm2, out_nodes };
    const int frag_per_layer = 4 * NCHUNK * 1024;   // uint4 per layer
    for (int l = 0; l < DEPTH_N; ++l) {
        k_edge_split<<<splitGrid, TPB>>>(nmchain[l], eh, src, rev_index);
        k_gemm_mma<<<gemmGrid, TPB, smem_bytes>>>(
            wfrag + (size_t)l * frag_per_layer, bs + (size_t)l * D_N,
            em, eh, dst, nmchain[l + 1], (l + 1 < DEPTH_N) ? 1 : 0);
    }
}

// round 14
// speedup vs baseline: 1.0470x; 1.0470x over previous
#include <cuda_runtime.h>
#include <cuda_bf16.h>
#include <cstdint>

// ChempropBlock: V=10000 nodes, E=160000 edges, D=512, DEPTH=3
// out = [node_hiddens (V*D) | eh (E*D)] fp32
//
// Per layer l:
//   k_edge_split: em_frag = split_bf16(nm[src] - relu(eh[rev])) in the GEMM's
//                 fragment tile layout (gather+convert off the GEMM path)
//   k_gemm_mma:   streaming 3-stage cp.async pipeline; eh += em @ W^T + b
//                 (in place); epilogue scatters relu(eh) into nm_next
//                 (plain into out_nodes on the last layer).
// GEMM math: mma.sync m16n8k16 bf16, 3-term split (D += A0B0 + A1B0 + A0B1).
// R14: MMA loop reverted to the R12 interleaved form (minimal register
// lifetimes; the R13 hoist cost ~35us/layer); k_setup launch-fusion kept.

#define V_N 10000
#define E_N 160000
#define D_N 512
#define DEPTH_N 3

#define TM 128
#define TN 128
#define KC 32
#define NCHUNK (D_N / KC)     // 16
#define NMB (E_N / TM)        // 1250 m-blocks
#define CH_U32 4096           // u32 per (mblock, chunk) fragment block
#define MB_U32 (NCHUNK * CH_U32)   // 65536 u32 per mblock

__device__ float g_nm0[(size_t)V_N * D_N];
__device__ float g_nm1[(size_t)V_N * D_N];
__device__ float g_nm2[(size_t)V_N * D_N];
// em fragment buffer: [mb(1250)][chunk(16)][sp(2)][row(128)][16 u32] = 327 MB
__device__ uint32_t g_em[(size_t)NMB * MB_U32];
// W fragments: [layer(3)][nblock(4)][chunk(16)][k16(2)][nb(16)][lane(32)] uint4
__device__ uint4 g_wfrag[3 * 4 * 16 * 2 * 16 * 32];

__device__ __forceinline__ uint32_t smem_u32(const void* p) {
    uint32_t a;
    asm("{ .reg .u64 t; cvta.to.shared.u64 t, %1; cvt.u32.u64 %0, t; }"
        : "=r"(a) : "l"(p));
    return a;
}
__device__ __forceinline__ uint32_t pack_bf2(float x, float y, float2& back) {
    __nv_bfloat162 h = __float22bfloat162_rn(make_float2(x, y));
    back = __bfloat1622float2(h);
    return *(uint32_t*)&h;
}
__device__ __forceinline__ uint32_t pack_bf2n(float x, float y) {
    __nv_bfloat162 h = __float22bfloat162_rn(make_float2(x, y));
    return *(uint32_t*)&h;
}
__device__ __forceinline__ void red_add_v4(float* addr, float4 v) {
    asm volatile("red.global.add.v4.f32 [%0], {%1, %2, %3, %4};"
                 :: "l"(addr), "f"(v.x), "f"(v.y), "f"(v.z), "f"(v.w)
                 : "memory");
}
__device__ __forceinline__ void red_add_v2(float* addr, float x, float y) {
    asm volatile("red.global.add.v2.f32 [%0], {%1, %2};"
                 :: "l"(addr), "f"(x), "f"(y)
                 : "memory");
}
__device__ __forceinline__ void ldmatrix_x4(uint32_t* r, uint32_t addr) {
    asm volatile("ldmatrix.sync.aligned.m8n8.x4.shared.b16 {%0,%1,%2,%3}, [%4];"
                 : "=r"(r[0]), "=r"(r[1]), "=r"(r[2]), "=r"(r[3])
                 : "r"(addr));
}
__device__ __forceinline__ void mma_bf16(float* d, const uint32_t* a,
                                         uint32_t b0, uint32_t b1) {
    asm volatile(
        "mma.sync.aligned.m16n8k16.row.col.f32.bf16.bf16.f32 "
        "{%0,%1,%2,%3}, {%4,%5,%6,%7}, {%8,%9}, {%0,%1,%2,%3};"
        : "+f"(d[0]), "+f"(d[1]), "+f"(d[2]), "+f"(d[3])
        : "r"(a[0]), "r"(a[1]), "r"(a[2]), "r"(a[3]), "r"(b0), "r"(b1));
}

#define CP_ASYNC_16(dst_u32, src_ptr) \
    asm volatile("cp.async.cg.shared.global [%0], [%1], 16;" \
                 :: "r"(dst_u32), "l"(src_ptr) : "memory")
#define CP_ASYNC_COMMIT() asm volatile("cp.async.commit_group;" ::: "memory")
#define CP_ASYNC_WAIT0()  asm volatile("cp.async.wait_group 0;" ::: "memory")
#define CP_ASYNC_WAIT1()  asm volatile("cp.async.wait_group 1;" ::: "memory")

// ---------------------------------------------------------------------------
// setup: zero nm0/nm1/nm2/out_nodes AND precompute W fragments, one launch.
// blocks [0, 20000): zeroing; blocks [20000, 20768): wfrag.
// ---------------------------------------------------------------------------
#define ZERO_BLKS 20000
__global__ void k_setup(const float* __restrict__ Ws,
                        float4* __restrict__ z0, float4* __restrict__ z1,
                        float4* __restrict__ z2, float4* __restrict__ z3) {
    const int bid = blockIdx.x;
    if (bid < ZERO_BLKS) {
        const int n4 = V_N * D_N / 4;          // 1,280,000
        int i = bid * 256 + threadIdx.x;       // < 5,120,000
        int which = i / n4;
        int off = i - which * n4;
        float4* p = (which == 0) ? z0 : (which == 1) ? z1
                  : (which == 2) ? z2 : z3;
        p[off] = make_float4(0.f, 0.f, 0.f, 0.f);
        return;
    }
    int t = (bid - ZERO_BLKS) * 256 + threadIdx.x;   // < 196608
    int lane  = t & 31;
    int nb    = (t >> 5) & 15;
    int k16   = (t >> 9) & 1;
    int chunk = (t >> 10) & 15;
    int nblk  = (t >> 14) & 3;
    int layer = t >> 16;
    int n = nblk * 128 + nb * 8 + (lane >> 2);
    int k = chunk * 32 + k16 * 16 + (lane & 3) * 2;
    const float* w = Ws + ((size_t)layer * D_N + n) * D_N + k;
    float w00 = w[0], w01 = w[1], w10 = w[8], w11 = w[9];
    float2 bk;
    uint4 o;
    o.x = pack_bf2(w00, w01, bk);
    o.z = pack_bf2n(w00 - bk.x, w01 - bk.y);
    o.y = pack_bf2(w10, w11, bk);
    o.w = pack_bf2n(w10 - bk.x, w11 - bk.y);
    g_wfrag[t] = o;
}

// eh0 = nf[src] + ef (written to d_out eh region); relu-scatter eh0 into nm
__global__ void k_init_eh_scatter(const float* __restrict__ nf,
                                  const float* __restrict__ ef,
                                  const int* __restrict__ src,
                                  const int* __restrict__ dst,
                                  float* __restrict__ eh,
                                  float* __restrict__ nm) {
    int idx = blockIdx.x * blockDim.x + threadIdx.x;   // < E*D/4
    int e = idx >> 7;
    int c = (idx & 127) << 2;
    int s = __ldg(&src[e]);
    const float4 a = *(const float4*)(nf + (size_t)s * D_N + c);
    const float4 b = *(const float4*)(ef + (size_t)e * D_N + c);
    float4 r; r.x = a.x + b.x; r.y = a.y + b.y; r.z = a.z + b.z; r.w = a.w + b.w;
    *(float4*)(eh + (size_t)e * D_N + c) = r;
    int d = __ldg(&dst[e]);
    float4 rr;
    rr.x = fmaxf(r.x, 0.f); rr.y = fmaxf(r.y, 0.f);
    rr.z = fmaxf(r.z, 0.f); rr.w = fmaxf(r.w, 0.f);
    red_add_v4(nm + (size_t)d * D_N + c, rr);
}

// ---------------------------------------------------------------------------
// em_frag writer (identical layout + math to R12)
// ---------------------------------------------------------------------------
__global__ void k_edge_split(const float* __restrict__ nm,
                             const float* __restrict__ eh,
                             const int* __restrict__ src,
                             const int* __restrict__ rev) {
    int g = blockIdx.x * blockDim.x + threadIdx.x;   // < E*8
    int row = g >> 3;
    int kp  = g & 7;
    int s = __ldg(&src[row]);
    int r = __ldg(&rev[row]);
    const float* nrow = nm + (size_t)s * D_N + kp * 4;
    const float* erow = eh + (size_t)r * D_N + kp * 4;
    const int mb = row >> 7;
    const int ri = row & 127;
    const int sw = ((ri >> 1) & 3) << 2;
    uint32_t* base = g_em + (size_t)mb * MB_U32 + ri * 16 + ((2 * kp) ^ sw);
#pragma unroll 4
    for (int c = 0; c < NCHUNK; ++c) {
        const float4 n4 = *(const float4*)(nrow + c * KC);
        const float4 e4 = *(const float4*)(erow + c * KC);
        float em0 = n4.x - fmaxf(e4.x, 0.f);
        float em1 = n4.y - fmaxf(e4.y, 0.f);
        float em2 = n4.z - fmaxf(e4.z, 0.f);
        float em3 = n4.w - fmaxf(e4.w, 0.f);
        float2 bk;
        uint2 s0, s1;
        s0.x = pack_bf2(em0, em1, bk);
        s1.x = pack_bf2n(em0 - bk.x, em1 - bk.y);
        s0.y = pack_bf2(em2, em3, bk);
        s1.y = pack_bf2n(em2 - bk.x, em3 - bk.y);
        *(uint2*)(base + c * CH_U32)        = s0;   // split-hi (sp=0)
        *(uint2*)(base + c * CH_U32 + 2048) = s1;   // split-lo (sp=1)
    }
}

// ---------------------------------------------------------------------------
// Streaming GEMM. smem (b32): [0..511] s_dst + pad; 3 stages of 8192:
//   stage: SA = [sp(2)][row(128)][16 u32] (4096), SB = [k16][nb][lane] uint4
// total 25088 u32 = 100352 B -> 2 CTA/SM.
// ---------------------------------------------------------------------------
#define STG_U32 8192
#define SMEM_U32 (512 + 3 * STG_U32)   // 25088

__global__ void __launch_bounds__(256, 2)
k_gemm_mma(const uint4* __restrict__ wf,
           const float* __restrict__ bias,
           const uint32_t* __restrict__ em,
           float* __restrict__ eh,             // in-place update
           const int* __restrict__ dst,
           float* __restrict__ scat,
           int do_relu) {
    extern __shared__ float smemf[];
    uint32_t* smemu = (uint32_t*)smemf;
    int* s_dst = (int*)smemf;

    const int tid = threadIdx.x;
    const int wid = tid >> 5;
    const int lid = tid & 31;
    const int mBase = blockIdx.y * TM;
    const int nBase = blockIdx.x * TN;
    const uint32_t* emb = em + (size_t)blockIdx.y * MB_U32;
    const uint4* wfn = wf + (size_t)blockIdx.x * (NCHUNK * 1024);

    if (tid < TM) s_dst[tid] = __ldg(&dst[mBase + tid]);
    // s_dst read only in the epilogue, long after the pipeline's barriers.

    const uint32_t sb = smem_u32(smemf);

    auto issue = [&](int c, int stg) {
        const uint32_t ab = sb + (512 + stg * STG_U32) * 4;
        const uint32_t* gA = emb + c * CH_U32;
#pragma unroll
        for (int q = 0; q < 4; ++q) {
            const int i = tid + q * 256;
            CP_ASYNC_16(ab + i * 16, gA + i * 4);
        }
        const uint32_t bb = ab + 4096 * 4;
        const uint4* gB = wfn + c * 1024;
#pragma unroll
        for (int q = 0; q < 4; ++q) {
            const int i = tid + q * 256;
            CP_ASYNC_16(bb + i * 16, gB + i);
        }
    };

    // ---- warp tiles: 2 (M) x 4 (N) of 64x32 ----
    const int wm  = (wid >> 2) * 64;
    const int wnb = (wid & 3) * 4;
    const int wn  = wnb * 8;

    const int lmrow = lid & 15;
    const int lmkh  = (lid >> 4) << 2;
    uint32_t lmOff[4], lmSw[4];
#pragma unroll
    for (int rbi = 0; rbi < 4; ++rbi) {
        const int row = wm + rbi * 16 + lmrow;
        lmOff[rbi] = row * 16;
        lmSw[rbi]  = ((row >> 1) & 3) << 2;
    }

    float acc[4][4][4];
#pragma unroll
    for (int i = 0; i < 4; ++i)
#pragma unroll
        for (int j = 0; j < 4; ++j)
#pragma unroll
            for (int k = 0; k < 4; ++k) acc[i][j][k] = 0.f;

    // 3-stage pipeline: issue(0),(1) up front; per chunk:
    //   wait (<=1, last chunk 0) -> barrier -> issue(c+2) -> MMA(c)
    issue(0, 0); CP_ASYNC_COMMIT();
    issue(1, 1); CP_ASYNC_COMMIT();

    for (int c = 0; c < NCHUNK; ++c) {
        const int stg = c % 3;
        if (c == NCHUNK - 1) { CP_ASYNC_WAIT0(); } else { CP_ASYNC_WAIT1(); }
        __syncthreads();
        if (c + 2 < NCHUNK) {
            issue(c + 2, (c + 2) % 3);
            CP_ASYNC_COMMIT();
        }

        const uint32_t sa_base = 512 + stg * STG_U32;
        const uint32_t sb_base = sa_base + 4096;
#pragma unroll
        for (int k16 = 0; k16 < 2; ++k16) {
            uint4 b[4];
#pragma unroll
            for (int nb = 0; nb < 4; ++nb)
                b[nb] = *(const uint4*)(smemu + sb_base +
                         ((k16 * 16 + wnb + nb) * 32 + lid) * 4);
#pragma unroll
            for (int rbi = 0; rbi < 4; ++rbi) {
                const uint32_t idx = (uint32_t)((k16 * 8) | lmkh) ^ lmSw[rbi];
                const uint32_t a0addr = sb + (sa_base + lmOff[rbi] + idx) * 4;
                uint32_t as0[4], as1[4];
                ldmatrix_x4(as0, a0addr);
                ldmatrix_x4(as1, a0addr + 2048 * 4);   // split-lo
#pragma unroll
                for (int nb = 0; nb < 4; ++nb)
                    mma_bf16(acc[rbi][nb], as0, b[nb].x, b[nb].y);
#pragma unroll
                for (int nb = 0; nb < 4; ++nb)
                    mma_bf16(acc[rbi][nb], as1, b[nb].x, b[nb].y);
#pragma unroll
                for (int nb = 0; nb < 4; ++nb)
                    mma_bf16(acc[rbi][nb], as0, b[nb].z, b[nb].w);
            }
        }
    }

    // ---- epilogue: eh += acc + bias (in place); fused scatter ----
    const int lr4 = lid >> 2;
    const int lm4 = lid & 3;
#pragma unroll
    for (int rbi = 0; rbi < 4; ++rbi) {
#pragma unroll
        for (int half = 0; half < 2; ++half) {
            const int mi = wm + rbi * 16 + half * 8 + lr4;
            const int m = mBase + mi;
            const int d = s_dst[mi];
            float* erow = eh + (size_t)m * D_N + nBase;
            float* srow = scat + (size_t)d * D_N + nBase;
#pragma unroll
            for (int nb = 0; nb < 4; ++nb) {
                const int cc = wn + nb * 8 + 2 * lm4;
                float2 e = *(const float2*)(erow + cc);
                e.x += acc[rbi][nb][half * 2 + 0] + __ldg(&bias[nBase + cc]);
                e.y += acc[rbi][nb][half * 2 + 1] + __ldg(&bias[nBase + cc + 1]);
                *(float2*)(erow + cc) = e;
                if (do_relu) {
                    red_add_v2(srow + cc, fmaxf(e.x, 0.f), fmaxf(e.y, 0.f));
                } else {
                    red_add_v2(srow + cc, e.x, e.y);
                }
            }
        }
    }
}

// ---------------------------------------------------------------------------
extern "C" void kernel_launch(void* const* d_in, const int* in_sizes, int n_in,
                              void* d_out, int out_size) {
    const float* node_feats = (const float*)d_in[0];
    const float* edge_feats = (const float*)d_in[1];
    const float* Ws         = (const float*)d_in[2];
    const float* bs         = (const float*)d_in[3];
    const int*   edge_index = (const int*)  d_in[4];
    const int*   rev_index  = (const int*)  d_in[5];

    const int* src = edge_index;
    const int* dst = edge_index + E_N;

    float* out_nodes = (float*)d_out;
    float* eh        = (float*)d_out + (size_t)V_N * D_N;   // in-place

    float *nm0 = nullptr, *nm1 = nullptr, *nm2 = nullptr;
    uint32_t* em = nullptr;
    cudaGetSymbolAddress((void**)&nm0, g_nm0);
    cudaGetSymbolAddress((void**)&nm1, g_nm1);
    cudaGetSymbolAddress((void**)&nm2, g_nm2);
    cudaGetSymbolAddress((void**)&em, g_em);
    uint4* wfrag = nullptr;
    cudaGetSymbolAddress((void**)&wfrag, g_wfrag);

    const int smem_bytes = SMEM_U32 * 4;    // 100352
    cudaFuncSetAttribute(k_gemm_mma,
                         cudaFuncAttributeMaxDynamicSharedMemorySize, smem_bytes);

    const int TPB = 256;
    const int edgeGrid  = (E_N * (D_N / 4)) / TPB;      // 80000
    const int splitGrid = (E_N * 8) / TPB;              // 5000
    dim3 gemmGrid(D_N / TN, E_N / TM);                  // (4, 1250)

    // launches: 0 setup(zero+wfrag), 1 init, 2 split0, 3 gemm0 <- ncu capture
    k_setup<<<ZERO_BLKS + 768, TPB>>>(Ws, (float4*)nm0, (float4*)nm1,
                                      (float4*)nm2, (float4*)out_nodes);
    k_init_eh_scatter<<<edgeGrid, TPB>>>(node_feats, edge_feats, src, dst,
                                         eh, nm0);

    float* nmchain[4] = { nm0, nm1, nm2, out_nodes };
    const int frag_per_layer = 4 * NCHUNK * 1024;   // uint4 per layer
    for (int l = 0; l < DEPTH_N; ++l) {
        k_edge_split<<<splitGrid, TPB>>>(nmchain[l], eh, src, rev_index);
        k_gemm_mma<<<gemmGrid, TPB, smem_bytes>>>(
            wfrag + (size_t)l * frag_per_layer, bs + (size_t)l * D_N,
            em, eh, dst, nmchain[l + 1], (l + 1 < DEPTH_N) ? 1 : 0);
    }
}

// round 15
// speedup vs baseline: 1.0860x; 1.0373x over previous
#include <cuda_runtime.h>
#include <cuda_bf16.h>
#include <cstdint>

// ChempropBlock: V=10000 nodes, E=160000 edges, D=512, DEPTH=3
// out = [node_hiddens (V*D) | eh (E*D)] fp32
//
// Per layer l:
//   k_edge_split: em_frag = split_bf16(nm[src] - relu(eh[rev])) in the GEMM's
//                 fragment tile layout (gather+convert off the GEMM path)
//   k_gemm_mma:   streaming 2-stage cp.async pipeline; eh += em @ W^T + b
//                 (in place); epilogue scatters relu(eh) into nm_next
//                 (plain into out_nodes on the last layer).
// GEMM math: mma.sync m16n8k16 bf16, 3-term split (D += A0B0 + A1B0 + A0B1).
// R15: GEMM reshaped to 128-thread CTAs (4 warps), TN=64, 4 CTA/SM ->
// quarter-size barrier domains, 4 independent pipelines per SM.

#define V_N 10000
#define E_N 160000
#define D_N 512
#define DEPTH_N 3

#define TM 128
#define TN 64
#define KC 32
#define NCHUNK (D_N / KC)     // 16
#define NMB (E_N / TM)        // 1250 m-blocks
#define CH_U32 4096           // u32 per (mblock, chunk) A-fragment block
#define MB_U32 (NCHUNK * CH_U32)   // 65536 u32 per mblock

__device__ float g_nm0[(size_t)V_N * D_N];
__device__ float g_nm1[(size_t)V_N * D_N];
__device__ float g_nm2[(size_t)V_N * D_N];
// em fragment buffer: [mb(1250)][chunk(16)][sp(2)][row(128)][16 u32] = 327 MB
__device__ uint32_t g_em[(size_t)NMB * MB_U32];
// W fragments: [layer(3)][nblk(8)][chunk(16)][k16(2)][nb(8)][lane(32)] uint4
__device__ uint4 g_wfrag[3 * 8 * 16 * 2 * 8 * 32];

__device__ __forceinline__ uint32_t smem_u32(const void* p) {
    uint32_t a;
    asm("{ .reg .u64 t; cvta.to.shared.u64 t, %1; cvt.u32.u64 %0, t; }"
        : "=r"(a) : "l"(p));
    return a;
}
__device__ __forceinline__ uint32_t pack_bf2(float x, float y, float2& back) {
    __nv_bfloat162 h = __float22bfloat162_rn(make_float2(x, y));
    back = __bfloat1622float2(h);
    return *(uint32_t*)&h;
}
__device__ __forceinline__ uint32_t pack_bf2n(float x, float y) {
    __nv_bfloat162 h = __float22bfloat162_rn(make_float2(x, y));
    return *(uint32_t*)&h;
}
__device__ __forceinline__ void red_add_v4(float* addr, float4 v) {
    asm volatile("red.global.add.v4.f32 [%0], {%1, %2, %3, %4};"
                 :: "l"(addr), "f"(v.x), "f"(v.y), "f"(v.z), "f"(v.w)
                 : "memory");
}
__device__ __forceinline__ void red_add_v2(float* addr, float x, float y) {
    asm volatile("red.global.add.v2.f32 [%0], {%1, %2};"
                 :: "l"(addr), "f"(x), "f"(y)
                 : "memory");
}
__device__ __forceinline__ void ldmatrix_x4(uint32_t* r, uint32_t addr) {
    asm volatile("ldmatrix.sync.aligned.m8n8.x4.shared.b16 {%0,%1,%2,%3}, [%4];"
                 : "=r"(r[0]), "=r"(r[1]), "=r"(r[2]), "=r"(r[3])
                 : "r"(addr));
}
__device__ __forceinline__ void mma_bf16(float* d, const uint32_t* a,
                                         uint32_t b0, uint32_t b1) {
    asm volatile(
        "mma.sync.aligned.m16n8k16.row.col.f32.bf16.bf16.f32 "
        "{%0,%1,%2,%3}, {%4,%5,%6,%7}, {%8,%9}, {%0,%1,%2,%3};"
        : "+f"(d[0]), "+f"(d[1]), "+f"(d[2]), "+f"(d[3])
        : "r"(a[0]), "r"(a[1]), "r"(a[2]), "r"(a[3]), "r"(b0), "r"(b1));
}

#define CP_ASYNC_16(dst_u32, src_ptr) \
    asm volatile("cp.async.cg.shared.global [%0], [%1], 16;" \
                 :: "r"(dst_u32), "l"(src_ptr) : "memory")
#define CP_ASYNC_COMMIT() asm volatile("cp.async.commit_group;" ::: "memory")
#define CP_ASYNC_WAIT0()  asm volatile("cp.async.wait_group 0;" ::: "memory")

// ---------------------------------------------------------------------------
// setup: zero nm0/nm1/nm2/out_nodes AND precompute W fragments, one launch.
// blocks [0, 20000): zeroing; blocks [20000, 20768): wfrag.
// ---------------------------------------------------------------------------
#define ZERO_BLKS 20000
__global__ void k_setup(const float* __restrict__ Ws,
                        float4* __restrict__ z0, float4* __restrict__ z1,
                        float4* __restrict__ z2, float4* __restrict__ z3) {
    const int bid = blockIdx.x;
    if (bid < ZERO_BLKS) {
        const int n4 = V_N * D_N / 4;          // 1,280,000
        int i = bid * 256 + threadIdx.x;       // < 5,120,000
        int which = i / n4;
        int off = i - which * n4;
        float4* p = (which == 0) ? z0 : (which == 1) ? z1
                  : (which == 2) ? z2 : z3;
        p[off] = make_float4(0.f, 0.f, 0.f, 0.f);
        return;
    }
    // W fragments, 64-wide n-blocks: [layer][nblk(8)][chunk(16)][k16][nb(8)][lane]
    int t = (bid - ZERO_BLKS) * 256 + threadIdx.x;   // < 196608
    int lane  = t & 31;
    int nb    = (t >> 5) & 7;
    int k16   = (t >> 8) & 1;
    int chunk = (t >> 9) & 15;
    int nblk  = (t >> 13) & 7;
    int layer = t >> 16;
    int n = nblk * 64 + nb * 8 + (lane >> 2);
    int k = chunk * 32 + k16 * 16 + (lane & 3) * 2;
    const float* w = Ws + ((size_t)layer * D_N + n) * D_N + k;
    float w00 = w[0], w01 = w[1], w10 = w[8], w11 = w[9];
    float2 bk;
    uint4 o;
    o.x = pack_bf2(w00, w01, bk);
    o.z = pack_bf2n(w00 - bk.x, w01 - bk.y);
    o.y = pack_bf2(w10, w11, bk);
    o.w = pack_bf2n(w10 - bk.x, w11 - bk.y);
    g_wfrag[t] = o;
}

// eh0 = nf[src] + ef (written to d_out eh region); relu-scatter eh0 into nm
__global__ void k_init_eh_scatter(const float* __restrict__ nf,
                                  const float* __restrict__ ef,
                                  const int* __restrict__ src,
                                  const int* __restrict__ dst,
                                  float* __restrict__ eh,
                                  float* __restrict__ nm) {
    int idx = blockIdx.x * blockDim.x + threadIdx.x;   // < E*D/4
    int e = idx >> 7;
    int c = (idx & 127) << 2;
    int s = __ldg(&src[e]);
    const float4 a = *(const float4*)(nf + (size_t)s * D_N + c);
    const float4 b = *(const float4*)(ef + (size_t)e * D_N + c);
    float4 r; r.x = a.x + b.x; r.y = a.y + b.y; r.z = a.z + b.z; r.w = a.w + b.w;
    *(float4*)(eh + (size_t)e * D_N + c) = r;
    int d = __ldg(&dst[e]);
    float4 rr;
    rr.x = fmaxf(r.x, 0.f); rr.y = fmaxf(r.y, 0.f);
    rr.z = fmaxf(r.z, 0.f); rr.w = fmaxf(r.w, 0.f);
    red_add_v4(nm + (size_t)d * D_N + c, rr);
}

// ---------------------------------------------------------------------------
// em_frag writer (layout identical to R12/R14)
// ---------------------------------------------------------------------------
__global__ void k_edge_split(const float* __restrict__ nm,
                             const float* __restrict__ eh,
                             const int* __restrict__ src,
                             const int* __restrict__ rev) {
    int g = blockIdx.x * blockDim.x + threadIdx.x;   // < E*8
    int row = g >> 3;
    int kp  = g & 7;
    int s = __ldg(&src[row]);
    int r = __ldg(&rev[row]);
    const float* nrow = nm + (size_t)s * D_N + kp * 4;
    const float* erow = eh + (size_t)r * D_N + kp * 4;
    const int mb = row >> 7;
    const int ri = row & 127;
    const int sw = ((ri >> 1) & 3) << 2;
    uint32_t* base = g_em + (size_t)mb * MB_U32 + ri * 16 + ((2 * kp) ^ sw);
#pragma unroll 4
    for (int c = 0; c < NCHUNK; ++c) {
        const float4 n4 = *(const float4*)(nrow + c * KC);
        const float4 e4 = *(const float4*)(erow + c * KC);
        float em0 = n4.x - fmaxf(e4.x, 0.f);
        float em1 = n4.y - fmaxf(e4.y, 0.f);
        float em2 = n4.z - fmaxf(e4.z, 0.f);
        float em3 = n4.w - fmaxf(e4.w, 0.f);
        float2 bk;
        uint2 s0, s1;
        s0.x = pack_bf2(em0, em1, bk);
        s1.x = pack_bf2n(em0 - bk.x, em1 - bk.y);
        s0.y = pack_bf2(em2, em3, bk);
        s1.y = pack_bf2n(em2 - bk.x, em3 - bk.y);
        *(uint2*)(base + c * CH_U32)        = s0;   // split-hi (sp=0)
        *(uint2*)(base + c * CH_U32 + 2048) = s1;   // split-lo (sp=1)
    }
}

// ---------------------------------------------------------------------------
// Streaming GEMM, 128 threads (4 warps), TN=64, 4 CTA/SM.
// smem (b32): [0..511] s_dst + pad; 2 stages of 6144:
//   stage: SA = [sp(2)][row(128)][16 u32] (4096), SB = [k16][nb(8)][lane] uint4
//          (2048)
// total 12800 u32 = 51200 B -> 4 CTA/SM (204.8 KB); regs 128 x 512 thr = full RF.
// ---------------------------------------------------------------------------
#define STG_U32 6144
#define SMEM_U32 (512 + 2 * STG_U32)   // 12800

__global__ void __launch_bounds__(128, 4)
k_gemm_mma(const uint4* __restrict__ wf,
           const float* __restrict__ bias,
           const uint32_t* __restrict__ em,
           float* __restrict__ eh,             // in-place update
           const int* __restrict__ dst,
           float* __restrict__ scat,
           int do_relu) {
    extern __shared__ float smemf[];
    uint32_t* smemu = (uint32_t*)smemf;
    int* s_dst = (int*)smemf;

    const int tid = threadIdx.x;
    const int wid = tid >> 5;            // 0..3
    const int lid = tid & 31;
    const int mBase = blockIdx.y * TM;
    const int nBase = blockIdx.x * TN;
    const uint32_t* emb = em + (size_t)blockIdx.y * MB_U32;
    const uint4* wfn = wf + (size_t)blockIdx.x * (NCHUNK * 512); // 512 uint4/chunk

    s_dst[tid] = __ldg(&dst[mBase + tid]);
    // s_dst read only in the epilogue, long after the pipeline's barriers.

    const uint32_t sb = smem_u32(smemf);

    auto issue = [&](int c, int stg) {
        const uint32_t ab = sb + (512 + stg * STG_U32) * 4;
        const uint32_t* gA = emb + c * CH_U32;
#pragma unroll
        for (int q = 0; q < 8; ++q) {           // 4096 u32 / 128 thr = 8x16B
            const int i = tid + q * 128;
            CP_ASYNC_16(ab + i * 16, gA + i * 4);
        }
        const uint32_t bb = ab + 4096 * 4;
        const uint4* gB = wfn + c * 512;
#pragma unroll
        for (int q = 0; q < 4; ++q) {           // 512 uint4 / 128 thr = 4x16B
            const int i = tid + q * 128;
            CP_ASYNC_16(bb + i * 16, gB + i);
        }
    };

    // ---- warp tiles: 2 (M) x 2 (N) of 64x32 ----
    const int wm  = (wid >> 1) * 64;
    const int wnb = (wid & 1) * 4;       // nb base (each nb = 8 cols)
    const int wn  = wnb * 8;

    const int lmrow = lid & 15;
    const int lmkh  = (lid >> 4) << 2;
    uint32_t lmOff[4], lmSw[4];
#pragma unroll
    for (int rbi = 0; rbi < 4; ++rbi) {
        const int row = wm + rbi * 16 + lmrow;
        lmOff[rbi] = row * 16;
        lmSw[rbi]  = ((row >> 1) & 3) << 2;
    }

    float acc[4][4][4];
#pragma unroll
    for (int i = 0; i < 4; ++i)
#pragma unroll
        for (int j = 0; j < 4; ++j)
#pragma unroll
            for (int k = 0; k < 4; ++k) acc[i][j][k] = 0.f;

    // 2-stage pipeline: issue(0) up front; per chunk:
    //   wait0 -> barrier -> issue(c+1) -> MMA(c)
    // stage (c+1)&1 was consumed by MMA(c-1), complete in all 4 warps before
    // this barrier -> overwrite safe; issue gets a full MMA phase to land.
    issue(0, 0); CP_ASYNC_COMMIT();

    for (int c = 0; c < NCHUNK; ++c) {
        const int stg = c & 1;
        CP_ASYNC_WAIT0();
        __syncthreads();
        if (c + 1 < NCHUNK) {
            issue(c + 1, stg ^ 1);
            CP_ASYNC_COMMIT();
        }

        const uint32_t sa_base = 512 + stg * STG_U32;
        const uint32_t sb_base = sa_base + 4096;
#pragma unroll
        for (int k16 = 0; k16 < 2; ++k16) {
            uint4 b[4];
#pragma unroll
            for (int nb = 0; nb < 4; ++nb)
                b[nb] = *(const uint4*)(smemu + sb_base +
                         ((k16 * 8 + wnb + nb) * 32 + lid) * 4);
#pragma unroll
            for (int rbi = 0; rbi < 4; ++rbi) {
                const uint32_t idx = (uint32_t)((k16 * 8) | lmkh) ^ lmSw[rbi];
                const uint32_t a0addr = sb + (sa_base + lmOff[rbi] + idx) * 4;
                uint32_t as0[4], as1[4];
                ldmatrix_x4(as0, a0addr);
                ldmatrix_x4(as1, a0addr + 2048 * 4);   // split-lo
#pragma unroll
                for (int nb = 0; nb < 4; ++nb)
                    mma_bf16(acc[rbi][nb], as0, b[nb].x, b[nb].y);
#pragma unroll
                for (int nb = 0; nb < 4; ++nb)
                    mma_bf16(acc[rbi][nb], as1, b[nb].x, b[nb].y);
#pragma unroll
                for (int nb = 0; nb < 4; ++nb)
                    mma_bf16(acc[rbi][nb], as0, b[nb].z, b[nb].w);
            }
        }
    }

    // ---- epilogue: eh += acc + bias (in place); fused scatter ----
    const int lr4 = lid >> 2;
    const int lm4 = lid & 3;
#pragma unroll
    for (int rbi = 0; rbi < 4; ++rbi) {
#pragma unroll
        for (int half = 0; half < 2; ++half) {
            const int mi = wm + rbi * 16 + half * 8 + lr4;
            const int m = mBase + mi;
            const int d = s_dst[mi];
            float* erow = eh + (size_t)m * D_N + nBase;
            float* srow = scat + (size_t)d * D_N + nBase;
#pragma unroll
            for (int nb = 0; nb < 4; ++nb) {
                const int cc = wn + nb * 8 + 2 * lm4;
                float2 e = *(const float2*)(erow + cc);
                e.x += acc[rbi][nb][half * 2 + 0] + __ldg(&bias[nBase + cc]);
                e.y += acc[rbi][nb][half * 2 + 1] + __ldg(&bias[nBase + cc + 1]);
                *(float2*)(erow + cc) = e;
                if (do_relu) {
                    red_add_v2(srow + cc, fmaxf(e.x, 0.f), fmaxf(e.y, 0.f));
                } else {
                    red_add_v2(srow + cc, e.x, e.y);
                }
            }
        }
    }
}

// ---------------------------------------------------------------------------
extern "C" void kernel_launch(void* const* d_in, const int* in_sizes, int n_in,
                              void* d_out, int out_size) {
    const float* node_feats = (const float*)d_in[0];
    const float* edge_feats = (const float*)d_in[1];
    const float* Ws         = (const float*)d_in[2];
    const float* bs         = (const float*)d_in[3];
    const int*   edge_index = (const int*)  d_in[4];
    const int*   rev_index  = (const int*)  d_in[5];

    const int* src = edge_index;
    const int* dst = edge_index + E_N;

    float* out_nodes = (float*)d_out;
    float* eh        = (float*)d_out + (size_t)V_N * D_N;   // in-place

    float *nm0 = nullptr, *nm1 = nullptr, *nm2 = nullptr;
    uint32_t* em = nullptr;
    cudaGetSymbolAddress((void**)&nm0, g_nm0);
    cudaGetSymbolAddress((void**)&nm1, g_nm1);
    cudaGetSymbolAddress((void**)&nm2, g_nm2);
    cudaGetSymbolAddress((void**)&em, g_em);
    uint4* wfrag = nullptr;
    cudaGetSymbolAddress((void**)&wfrag, g_wfrag);

    const int smem_bytes = SMEM_U32 * 4;    // 51200
    cudaFuncSetAttribute(k_gemm_mma,
                         cudaFuncAttributeMaxDynamicSharedMemorySize, smem_bytes);

    const int TPB = 256;
    const int edgeGrid  = (E_N * (D_N / 4)) / TPB;      // 80000
    const int splitGrid = (E_N * 8) / TPB;              // 5000
    dim3 gemmGrid(D_N / TN, E_N / TM);                  // (8, 1250)

    // launches: 0 setup(zero+wfrag), 1 init, 2 split0, 3 gemm0 <- ncu capture
    k_setup<<<ZERO_BLKS + 768, TPB>>>(Ws, (float4*)nm0, (float4*)nm1,
                                      (float4*)nm2, (float4*)out_nodes);
    k_init_eh_scatter<<<edgeGrid, TPB>>>(node_feats, edge_feats, src, dst,
                                         eh, nm0);

    float* nmchain[4] = { nm0, nm1, nm2, out_nodes };
    const int frag_per_layer = 8 * NCHUNK * 512;   // uint4 per layer
    for (int l = 0; l < DEPTH_N; ++l) {
        k_edge_split<<<splitGrid, TPB>>>(nmchain[l], eh, src, rev_index);
        k_gemm_mma<<<gemmGrid, 128, smem_bytes>>>(
            wfrag + (size_t)l * frag_per_layer, bs + (size_t)l * D_N,
            em, eh, dst, nmchain[l + 1], (l + 1 < DEPTH_N) ? 1 : 0);
    }
}